// round 15
// baseline (speedup 1.0000x reference)
#include <cuda_runtime.h>

// Problem shape (fixed by the reference)
#define S 32768
#define H 1024
#define B1 444            // 3 CTAs/SM x 148 SMs; launch_bounds(256,3) guarantees co-residency
#define TPB 256
#define WPB 8
#define NF4 (H / 4)
#define NWARPS (B1 * WPB) // 3552

__device__ float4 g_part[NF4][B1];
__device__ unsigned int g_cnt;   // monotone epoch counter (graph-replay safe)

__global__ __launch_bounds__(TPB, 3)
void cosattn_fused(const float* __restrict__ query,
                   const float* __restrict__ keys,
                   float* __restrict__ out) {
    __shared__ float q_s[H];             // 4 KB
    __shared__ float warp_ctx[WPB][H];   // 32 KB  (36 KB/CTA x 3 = 108 KB <= 228)

    const int tid  = threadIdx.x;
    const int wid  = tid >> 5;
    const int lane = tid & 31;
    const int gwarp = blockIdx.x * WPB + wid;   // < 3552 < S

    for (int i = tid; i < NF4; i += TPB)
        ((float4*)q_s)[i] = ((const float4*)query)[i];
    __syncthreads();

    const float4* qs4 = (const float4*)q_s;
    float qss = 0.f;
#pragma unroll
    for (int j = 0; j < 8; j++) {
        float4 q = qs4[lane + 32 * j];
        qss += q.x * q.x + q.y * q.y + q.z * q.z + q.w * q.w;
    }
#pragma unroll
    for (int o = 16; o > 0; o >>= 1)
        qss += __shfl_xor_sync(0xffffffffu, qss, o);
    const float qn_inv = rsqrtf(qss);

    float4 acc[8];
#pragma unroll
    for (int j = 0; j < 8; j++) acc[j] = make_float4(0.f, 0.f, 0.f, 0.f);

    // ---- Main loop: single kv buffer, front-batched LDG.128, one row per iter ----
    for (int row = gwarp; row < S; row += NWARPS) {
        const float4* k4 = (const float4*)(keys + (size_t)row * H);
        float4 kv[8];
#pragma unroll
        for (int j = 0; j < 8; j++) kv[j] = k4[lane + 32 * j];

        float dot = 0.f, ss = 0.f;
#pragma unroll
        for (int j = 0; j < 8; j++) {
            float4 q = qs4[lane + 32 * j];
            dot += q.x * kv[j].x + q.y * kv[j].y + q.z * kv[j].z + q.w * kv[j].w;
            ss  += kv[j].x * kv[j].x + kv[j].y * kv[j].y
                 + kv[j].z * kv[j].z + kv[j].w * kv[j].w;
        }
#pragma unroll
        for (int o = 16; o > 0; o >>= 1) {
            dot += __shfl_xor_sync(0xffffffffu, dot, o);
            ss  += __shfl_xor_sync(0xffffffffu, ss, o);
        }
        const float cosv = dot * qn_inv * rsqrtf(ss);

#pragma unroll
        for (int j = 0; j < 8; j++) {
            acc[j].x += cosv * kv[j].x;
            acc[j].y += cosv * kv[j].y;
            acc[j].z += cosv * kv[j].z;
            acc[j].w += cosv * kv[j].w;
        }
    }

    // Block-level reduce via smem.
    float4* wctx4 = (float4*)warp_ctx[wid];
#pragma unroll
    for (int j = 0; j < 8; j++) wctx4[lane + 32 * j] = acc[j];
    __syncthreads();

    float4 sum = make_float4(0.f, 0.f, 0.f, 0.f);
#pragma unroll
    for (int w = 0; w < WPB; w++) {
        float4 v = ((const float4*)warp_ctx[w])[tid];
        sum.x += v.x; sum.y += v.y; sum.z += v.z; sum.w += v.w;
    }
    g_part[tid][blockIdx.x] = sum;

    // ---- Grid barrier (444 co-resident blocks) ----
    __threadfence();
    __syncthreads();
    if (tid == 0) {
        unsigned int old = atomicAdd(&g_cnt, 1u);
        unsigned int target = old - (old % B1) + B1;
        while (*(volatile unsigned int*)&g_cnt < target)
            __nanosleep(64);
    }
    __syncthreads();
    __threadfence();

    // ---- Phase 2: block b < 256 reduces float4-column b over 444 partials ----
    const int b = blockIdx.x;
    if (b < NF4) {
        float4 a = make_float4(0.f, 0.f, 0.f, 0.f);
        for (int r = tid; r < B1; r += TPB) {    // coalesced contiguous float4
            float4 v = g_part[b][r];
            a.x += v.x; a.y += v.y; a.z += v.z; a.w += v.w;
        }
        // Warp butterfly then cross-warp via smem (cheap: 8 partials).
#pragma unroll
        for (int o = 16; o > 0; o >>= 1) {
            a.x += __shfl_xor_sync(0xffffffffu, a.x, o);
            a.y += __shfl_xor_sync(0xffffffffu, a.y, o);
            a.z += __shfl_xor_sync(0xffffffffu, a.z, o);
            a.w += __shfl_xor_sync(0xffffffffu, a.w, o);
        }
        float4* red = (float4*)warp_ctx[0];
        if (lane == 0) red[wid] = a;
        __syncthreads();
        if (tid == 0) {
            float4 t = red[0];
#pragma unroll
            for (int w = 1; w < WPB; w++) {
                float4 o = red[w];
                t.x += o.x; t.y += o.y; t.z += o.z; t.w += o.w;
            }
            ((float4*)out)[b] = t;
        }
    }
}

extern "C" void kernel_launch(void* const* d_in, const int* in_sizes, int n_in,
                              void* d_out, int out_size) {
    const float* query = (const float*)d_in[0];  // [1, 1024]
    const float* keys  = (const float*)d_in[1];  // [32768, 1024]
    float* out = (float*)d_out;                  // [1, 1024]

    cosattn_fused<<<B1, TPB>>>(query, keys, out);
}

// round 16
// speedup vs baseline: 1.3399x; 1.3399x over previous
#include <cuda_runtime.h>

// Problem shape (fixed by the reference)
#define S 32768
#define H 1024
#define B1 296            // stage-1 blocks (2 per SM on 148 SMs)
#define TPB 256
#define WPB 8
#define NF4 (H / 4)
#define NWARPS (B1 * WPB) // 2368

// Transposed partials: g_part[f4col][block] -> contiguous per column for stage 2.
__device__ float4 g_part[NF4][B1];

__global__ __launch_bounds__(TPB, 2)
void cosattn_stage1(const float* __restrict__ query,
                    const float* __restrict__ keys) {
    __shared__ float warp_ctx[WPB][H];   // 32 KB

    const int tid  = threadIdx.x;
    const int wid  = tid >> 5;
    const int lane = tid & 31;
    const int gwarp = blockIdx.x * WPB + wid;

    // Query in registers (L1/L2-hot across warps; one-time cost).
    const float4* q4 = (const float4*)query;
    float4 qv[8];
    float qss = 0.f;
#pragma unroll
    for (int j = 0; j < 8; j++) {
        qv[j] = q4[lane + 32 * j];
        qss += qv[j].x * qv[j].x + qv[j].y * qv[j].y
             + qv[j].z * qv[j].z + qv[j].w * qv[j].w;
    }
#pragma unroll
    for (int o = 16; o > 0; o >>= 1)
        qss += __shfl_xor_sync(0xffffffffu, qss, o);
    const float qn_inv = rsqrtf(qss);

    float4 acc[8];
#pragma unroll
    for (int j = 0; j < 8; j++) acc[j] = make_float4(0.f, 0.f, 0.f, 0.f);

    for (int row = gwarp; row < S; row += NWARPS) {
        const float4* k4 = (const float4*)(keys + (size_t)row * H);
        float4 kv[8];
#pragma unroll
        for (int j = 0; j < 8; j++) kv[j] = k4[lane + 32 * j];

        float dot = 0.f, ss = 0.f;
#pragma unroll
        for (int j = 0; j < 8; j++) {
            dot += qv[j].x * kv[j].x + qv[j].y * kv[j].y
                 + qv[j].z * kv[j].z + qv[j].w * kv[j].w;
            ss  += kv[j].x * kv[j].x + kv[j].y * kv[j].y
                 + kv[j].z * kv[j].z + kv[j].w * kv[j].w;
        }
#pragma unroll
        for (int o = 16; o > 0; o >>= 1) {
            dot += __shfl_xor_sync(0xffffffffu, dot, o);
            ss  += __shfl_xor_sync(0xffffffffu, ss, o);
        }
        const float cosv = dot * qn_inv * rsqrtf(ss);

#pragma unroll
        for (int j = 0; j < 8; j++) {
            acc[j].x += cosv * kv[j].x;
            acc[j].y += cosv * kv[j].y;
            acc[j].z += cosv * kv[j].z;
            acc[j].w += cosv * kv[j].w;
        }
    }

    // Block-level reduce via smem, then transposed partial store.
    float4* wctx4 = (float4*)warp_ctx[wid];
#pragma unroll
    for (int j = 0; j < 8; j++) wctx4[lane + 32 * j] = acc[j];
    __syncthreads();

    float4 sum = make_float4(0.f, 0.f, 0.f, 0.f);
#pragma unroll
    for (int w = 0; w < WPB; w++) {
        float4 v = ((const float4*)warp_ctx[w])[tid];
        sum.x += v.x; sum.y += v.y; sum.z += v.z; sum.w += v.w;
    }
    g_part[tid][blockIdx.x] = sum;   // column-major: stage 2 reads contiguously
}

// Stage 2: one block per float4 column; 296 contiguous float4 from warm L2.
__global__ __launch_bounds__(128, 8)
void cosattn_stage2(float* __restrict__ out) {
    const int c    = blockIdx.x;     // 0..255
    const int tid  = threadIdx.x;    // 128
    const int wid  = tid >> 5;
    const int lane = tid & 31;

    float4 a = make_float4(0.f, 0.f, 0.f, 0.f);
    for (int r = tid; r < B1; r += 128) {      // coalesced contiguous float4
        float4 v = g_part[c][r];
        a.x += v.x; a.y += v.y; a.z += v.z; a.w += v.w;
    }
#pragma unroll
    for (int o = 16; o > 0; o >>= 1) {
        a.x += __shfl_xor_sync(0xffffffffu, a.x, o);
        a.y += __shfl_xor_sync(0xffffffffu, a.y, o);
        a.z += __shfl_xor_sync(0xffffffffu, a.z, o);
        a.w += __shfl_xor_sync(0xffffffffu, a.w, o);
    }

    __shared__ float4 red[4];
    if (lane == 0) red[wid] = a;
    __syncthreads();
    if (tid == 0) {
        float4 t = red[0];
#pragma unroll
        for (int w = 1; w < 4; w++) {
            float4 o = red[w];
            t.x += o.x; t.y += o.y; t.z += o.z; t.w += o.w;
        }
        ((float4*)out)[c] = t;
    }
}

extern "C" void kernel_launch(void* const* d_in, const int* in_sizes, int n_in,
                              void* d_out, int out_size) {
    const float* query = (const float*)d_in[0];  // [1, 1024]
    const float* keys  = (const float*)d_in[1];  // [32768, 1024]
    float* out = (float*)d_out;                  // [1, 1024]

    cosattn_stage1<<<B1, TPB>>>(query, keys);
    cosattn_stage2<<<NF4, 128>>>(out);
}

// round 17
// speedup vs baseline: 1.3458x; 1.0044x over previous
#include <cuda_runtime.h>

// Problem shape (fixed by the reference)
#define S 32768
#define H 1024
#define B1 148            // stage-1 blocks: 1 CTA/SM, 16 warps/SM (same as best config)
#define TPB 512
#define WPB 16
#define NF4 (H / 4)
#define NWARPS (B1 * WPB) // 2368 (identical row partitioning to R15)

#define SMEM_BYTES (WPB * H * 4)   // 64 KB dynamic (above 48KB static limit)

// Transposed partials: g_part[f4col][block] -> contiguous per column for stage 2.
__device__ float4 g_part[NF4][B1];

extern __shared__ float warp_ctx[];   // [WPB][H]

__global__ __launch_bounds__(TPB, 1)
void cosattn_stage1(const float* __restrict__ query,
                    const float* __restrict__ keys) {
    const int tid  = threadIdx.x;
    const int wid  = tid >> 5;
    const int lane = tid & 31;
    const int gwarp = blockIdx.x * WPB + wid;   // < 2368

    // Query in registers (one-time L1/L2-hot load).
    const float4* q4 = (const float4*)query;
    float4 qv[8];
    float qss = 0.f;
#pragma unroll
    for (int j = 0; j < 8; j++) {
        qv[j] = q4[lane + 32 * j];
        qss += qv[j].x * qv[j].x + qv[j].y * qv[j].y
             + qv[j].z * qv[j].z + qv[j].w * qv[j].w;
    }
#pragma unroll
    for (int o = 16; o > 0; o >>= 1)
        qss += __shfl_xor_sync(0xffffffffu, qss, o);
    const float qn_inv = rsqrtf(qss);

    float4 acc[8];
#pragma unroll
    for (int j = 0; j < 8; j++) acc[j] = make_float4(0.f, 0.f, 0.f, 0.f);

    for (int row = gwarp; row < S; row += NWARPS) {
        const float4* k4 = (const float4*)(keys + (size_t)row * H);
        float4 kv[8];
#pragma unroll
        for (int j = 0; j < 8; j++) kv[j] = k4[lane + 32 * j];

        float dot = 0.f, ss = 0.f;
#pragma unroll
        for (int j = 0; j < 8; j++) {
            dot += qv[j].x * kv[j].x + qv[j].y * kv[j].y
                 + qv[j].z * kv[j].z + qv[j].w * kv[j].w;
            ss  += kv[j].x * kv[j].x + kv[j].y * kv[j].y
                 + kv[j].z * kv[j].z + kv[j].w * kv[j].w;
        }
#pragma unroll
        for (int o = 16; o > 0; o >>= 1) {
            dot += __shfl_xor_sync(0xffffffffu, dot, o);
            ss  += __shfl_xor_sync(0xffffffffu, ss, o);
        }
        const float cosv = dot * qn_inv * rsqrtf(ss);

#pragma unroll
        for (int j = 0; j < 8; j++) {
            acc[j].x += cosv * kv[j].x;
            acc[j].y += cosv * kv[j].y;
            acc[j].z += cosv * kv[j].z;
            acc[j].w += cosv * kv[j].w;
        }
    }

    // Block-level reduce: 16 warp slices in smem; thread tid<256 sums its column.
    float4* wctx4 = (float4*)(warp_ctx + wid * H);
#pragma unroll
    for (int j = 0; j < 8; j++) wctx4[lane + 32 * j] = acc[j];
    __syncthreads();

    if (tid < NF4) {
        float4 sum = make_float4(0.f, 0.f, 0.f, 0.f);
#pragma unroll
        for (int w = 0; w < WPB; w++) {
            float4 v = ((const float4*)(warp_ctx + w * H))[tid];
            sum.x += v.x; sum.y += v.y; sum.z += v.z; sum.w += v.w;
        }
        g_part[tid][blockIdx.x] = sum;   // column-major for stage-2 coalescing
    }

    // PDL: allow stage 2 to begin launching (its grid-sync still waits for our stores).
    cudaTriggerProgrammaticLaunchCompletion();
}

// Stage 2: one block per float4 column; 148 contiguous float4 from warm L2.
__global__ __launch_bounds__(128, 8)
void cosattn_stage2(float* __restrict__ out) {
    const int c    = blockIdx.x;     // 0..255
    const int tid  = threadIdx.x;    // 128
    const int wid  = tid >> 5;
    const int lane = tid & 31;

    // Wait until stage 1's memory is visible (PDL dependency sync).
    cudaGridDependencySynchronize();

    float4 a = make_float4(0.f, 0.f, 0.f, 0.f);
    for (int r = tid; r < B1; r += 128) {      // 148 -> at most 2 iters, coalesced
        float4 v = g_part[c][r];
        a.x += v.x; a.y += v.y; a.z += v.z; a.w += v.w;
    }
#pragma unroll
    for (int o = 16; o > 0; o >>= 1) {
        a.x += __shfl_xor_sync(0xffffffffu, a.x, o);
        a.y += __shfl_xor_sync(0xffffffffu, a.y, o);
        a.z += __shfl_xor_sync(0xffffffffu, a.z, o);
        a.w += __shfl_xor_sync(0xffffffffu, a.w, o);
    }

    __shared__ float4 red[4];
    if (lane == 0) red[wid] = a;
    __syncthreads();
    if (tid == 0) {
        float4 t = red[0];
#pragma unroll
        for (int w = 1; w < 4; w++) {
            float4 o = red[w];
            t.x += o.x; t.y += o.y; t.z += o.z; t.w += o.w;
        }
        ((float4*)out)[c] = t;
    }
}

extern "C" void kernel_launch(void* const* d_in, const int* in_sizes, int n_in,
                              void* d_out, int out_size) {
    const float* query = (const float*)d_in[0];  // [1, 1024]
    const float* keys  = (const float*)d_in[1];  // [32768, 1024]
    float* out = (float*)d_out;                  // [1, 1024]

    static int configured = 0;
    if (!configured) {
        cudaFuncSetAttribute(cosattn_stage1,
                             cudaFuncAttributeMaxDynamicSharedMemorySize, SMEM_BYTES);
        configured = 1;
    }

    cosattn_stage1<<<B1, TPB, SMEM_BYTES>>>(query, keys);

    // Stage 2 with programmatic dependent launch (overlaps launch with stage-1 tail).
    cudaLaunchConfig_t cfg = {};
    cfg.gridDim = dim3(NF4);
    cfg.blockDim = dim3(128);
    cfg.dynamicSmemBytes = 0;
    cfg.stream = 0;
    cudaLaunchAttribute attr[1];
    attr[0].id = cudaLaunchAttributeProgrammaticStreamSerialization;
    attr[0].val.programmaticStreamSerializationAllowed = 1;
    cfg.attrs = attr;
    cfg.numAttrs = 1;
    cudaLaunchKernelEx(&cfg, cosattn_stage2, out);
}